// round 6
// baseline (speedup 1.0000x reference)
#include <cuda_runtime.h>
#include <cstdint>

typedef unsigned long long ull;
#define THREADS 512

// tile: 56 output cols x 12 output rows (28 low-res cols x 6 low-res rows step)
// smem (bytes):
//   xb float [16 ic][9 rows][34]   @ 0       = 19584
//   wb ull   [16 ic][16 oc][10]    @ 19584   = 20480   (dup-packed, pass-ordered taps)
//   u  ull   [16 oc][15 zr][28]    @ 40064   = 53760   (horizontal-FIR'd rows, col-pairs)
#define XB_ST   34
#define WB_OFF  19584
#define U_OFF   40064
#define U_ST    28
#define U_OC    (15 * U_ST)
#define SMEM_BYTES 93824

__device__ __forceinline__ ull packf2(float a, float b) {
    ull r; asm("mov.b64 %0, {%1, %2};" : "=l"(r) : "f"(a), "f"(b)); return r;
}
__device__ __forceinline__ ull pack2(float v) {
    ull r; asm("mov.b64 %0, {%1, %1};" : "=l"(r) : "f"(v)); return r;
}
__device__ __forceinline__ void fma2(ull &acc, ull a, ull b) {
    asm("fma.rn.f32x2 %0, %1, %2, %0;" : "+l"(acc) : "l"(a), "l"(b));
}
__device__ __forceinline__ float lo32(ull v) {
    float f; asm("{ .reg .b32 t; mov.b64 {%0, t}, %1; }" : "=f"(f) : "l"(v)); return f;
}
__device__ __forceinline__ float hi32(ull v) {
    float f; asm("{ .reg .b32 t; mov.b64 {t, %0}, %1; }" : "=f"(f) : "l"(v)); return f;
}

__global__ __launch_bounds__(THREADS, 2)
void conv_resample_v6(const float* __restrict__ x, const float* __restrict__ f,
                      const float* __restrict__ w, float* __restrict__ out) {
    extern __shared__ char sm[];
    float* xb = (float*)sm;
    ull* wb = (ull*)(sm + WB_OFF);
    ull* ub = (ull*)(sm + U_OFF);

    const int tid = threadIdx.x;
    const int wid = tid >> 5, ln = tid & 31;
    const int rt = blockIdx.x / 10, ct = blockIdx.x % 10;
    const int g = blockIdx.y, n = blockIdx.z;
    const int a0 = rt * 6;           // low-res row origin (12 output rows)
    const int b0 = ct * 28;          // low-res col origin (56 output cols)

    // ---- stage 1: x tile [16 ic][9 rows][33 cols] (cols b0-2..b0+30, rows a0-2..a0+6) ----
    const float* xg = x + ((size_t)(n * 128 + g * 16)) * 65536;
    for (int i = tid; i < 16 * 9 * 33; i += THREADS) {
        int c = i % 33;
        int rr = (i / 33) % 9;
        int ic = i / 297;
        int gm = a0 - 2 + rr, gq = b0 - 2 + c;
        float v = (gm >= 0 && gm < 256 && gq >= 0 && gq < 256)
                    ? xg[ic * 65536 + gm * 256 + gq] : 0.f;
        xb[(ic * 9 + rr) * XB_ST + c] = v;
    }
    // ---- weights dup-packed, pass-ordered taps [w0,w1,w2,w6,w7,w8,w3,w4,w5,0] ----
    {
        const int map[9] = {0, 1, 2, 6, 7, 8, 3, 4, 5};
        const float* wg = w + (size_t)(g * 16) * 144;
        for (int i = tid; i < 16 * 16 * 10; i += THREADS) {
            int j = i % 10;
            int oc = (i / 10) % 16;
            int ic = i / 160;
            float v = (j < 9) ? wg[(oc * 16 + ic) * 9 + map[j]] : 0.f;
            wb[i] = pack2(v);
        }
    }
    float f0 = __ldg(f), f1 = __ldg(f + 1), f2 = __ldg(f + 2), f3 = __ldg(f + 3);
    ull gq0 = pack2(2.f * f3), gq1 = pack2(2.f * f2),
        gq2 = pack2(2.f * f1), gq3 = pack2(2.f * f0);
    __syncthreads();

    // ---- stage 2: warp = (ocg, rb); half-lane h = oc parity, m = col-pair ----
    {
        const int ocg = wid >> 1, rb = wid & 1;
        const int h = ln >> 4, m = ln & 15;
        const int oc = ocg * 2 + h;
        const int pr0 = rb * 4;                 // 4 position rows per block

        ull acc[4][4];
#pragma unroll
        for (int r = 0; r < 4; ++r) acc[r][0] = acc[r][1] = acc[r][2] = acc[r][3] = 0ull;

        for (int ic = 0; ic < 16; ++ic) {
            const ull* wp = wb + (ic * 16 + oc) * 10;
            // ---- pass A: P00, P01 (taps w0,w1,w2,w6,w7,w8) ----
            {
                ulonglong2 W01 = *(const ulonglong2*)(wp);      // (w0, w1)
                ulonglong2 W26 = *(const ulonglong2*)(wp + 2);  // (w2, w6)
                ulonglong2 W78 = *(const ulonglong2*)(wp + 4);  // (w7, w8)
                const float* xr = xb + (ic * 9 + pr0) * XB_ST + 2 * m;
                float2 A = *(const float2*)xr;
                float e = __shfl_sync(0xffffffffu, A.x, ln + 1);
                ull xa = *(ull*)&A;
                ull xbv = packf2(A.y, e);
#pragma unroll
                for (int r = 0; r < 4; ++r) {
                    xr += XB_ST;
                    float2 B = *(const float2*)xr;
                    float eb = __shfl_sync(0xffffffffu, B.x, ln + 1);
                    ull ya = *(ull*)&B;
                    ull ybv = packf2(B.y, eb);
                    fma2(acc[r][0], xa,  W01.x);
                    fma2(acc[r][0], xbv, W26.x);
                    fma2(acc[r][0], ya,  W26.y);
                    fma2(acc[r][0], ybv, W78.y);
                    fma2(acc[r][1], xbv, W01.y);
                    fma2(acc[r][1], ybv, W78.x);
                    xa = ya; xbv = ybv;
                }
            }
            // ---- pass B: P10, P11 (taps w3,w4,w5) — only "y" rows pr0+1..pr0+4 ----
            {
                ulonglong2 W34 = *(const ulonglong2*)(wp + 6);  // (w3, w4)
                ull W5 = wp[8];
                const float* xr = xb + (ic * 9 + pr0 + 1) * XB_ST + 2 * m;
#pragma unroll
                for (int r = 0; r < 4; ++r) {
                    float2 B = *(const float2*)xr;
                    float eb = __shfl_sync(0xffffffffu, B.x, ln + 1);
                    ull ya = *(ull*)&B;
                    ull ybv = packf2(B.y, eb);
                    fma2(acc[r][2], ya,  W34.x);
                    fma2(acc[r][2], ybv, W5);
                    fma2(acc[r][3], ybv, W34.y);
                    xr += XB_ST;
                }
            }
        }

        // ---- horizontal FIR via shuffles; store u rows (zr = 2*(pr0+r)+py) ----
#pragma unroll
        for (int r = 0; r < 4; ++r) {
#pragma unroll
            for (int py = 0; py < 2; ++py) {
                ull za = acc[r][py ? 2 : 0];   // px0: (z[4m], z[4m+2])
                ull zc = acc[r][py ? 3 : 1];   // px1: (z[4m+1], z[4m+3])
                float a0x = lo32(za), a0y = hi32(za);
                float a1x = lo32(zc), a1y = hi32(zc);
                float n0x = __shfl_sync(0xffffffffu, a0x, ln + 1);
                float n1x = __shfl_sync(0xffffffffu, a1x, ln + 1);
                float n0y = __shfl_sync(0xffffffffu, a0y, ln + 1);
                float n1y = __shfl_sync(0xffffffffu, a1y, ln + 1);
                ull p1 = packf2(a1x, a0y), p2 = packf2(a0y, a1y);
                ull p3 = packf2(a1y, n0x), p4 = packf2(n0x, n1x);
                ull p5 = packf2(n1x, n0y), p6 = packf2(n0y, n1y);
                ull u01 = 0ull, u23 = 0ull;
                fma2(u01, p1, gq0); fma2(u01, p2, gq1);
                fma2(u01, p3, gq2); fma2(u01, p4, gq3);
                fma2(u23, p3, gq0); fma2(u23, p4, gq1);
                fma2(u23, p5, gq2); fma2(u23, p6, gq3);
                int zr = 2 * (pr0 + r) + py;
                if (zr >= 1 && m < 14) {
                    ulonglong2 uu; uu.x = u01; uu.y = u23;
                    *(ulonglong2*)(ub + (size_t)(oc * 15 + zr - 1) * U_ST + 2 * m) = uu;
                }
            }
        }
    }
    __syncthreads();

    // ---- stage 3: vertical FIR, warp = oc, lane = output col-pair ----
    {
        const int oc = wid;
        const int k = (ln < 28) ? ln : 27;
        const bool valid = (ln < 28) && (2 * b0 + 2 * ln < 512);
        const ull* up = ub + (size_t)oc * U_OC + k;
        ull r0 = up[0], r1 = up[U_ST], r2 = up[2 * U_ST];
        up += 3 * U_ST;
        float* og = out + ((size_t)(n * 128 + g * 16 + oc)) * 262144 + 2 * b0 + 2 * ln;
#pragma unroll
        for (int oy = 0; oy < 12; ++oy) {
            ull r3 = up[0]; up += U_ST;
            ull y = 0ull;
            fma2(y, r0, gq0); fma2(y, r1, gq1);
            fma2(y, r2, gq2); fma2(y, r3, gq3);
            r0 = r1; r1 = r2; r2 = r3;
            int gy = 2 * a0 + oy;
            if (valid && gy < 512)
                *(float2*)(og + (size_t)gy * 512) = *(float2*)&y;
        }
    }
}

extern "C" void kernel_launch(void* const* d_in, const int* in_sizes, int n_in,
                              void* d_out, int out_size) {
    const float* x = (const float*)d_in[0];
    const float* f = (const float*)d_in[1];
    const float* w = (const float*)d_in[2];
    float* out = (float*)d_out;

    cudaFuncSetAttribute(conv_resample_v6,
                         cudaFuncAttributeMaxDynamicSharedMemorySize, SMEM_BYTES);
    dim3 grid(43 * 10, 8, 4);   // 43 row-tiles x 10 col-tiles, groups, batch
    conv_resample_v6<<<grid, THREADS, SMEM_BYTES>>>(x, f, w, out);
}

// round 7
// speedup vs baseline: 1.1238x; 1.1238x over previous
#include <cuda_runtime.h>
#include <cstdint>

typedef unsigned long long ull;
#define THREADS 256

// tile: 4 low-res rows x 30 low-res cols -> 8 x 60 outputs, 16 oc
// smem:
//   xb float [16 ic][7 rows][33 cols]    @ 0      = 14784 B
//   wb ull   [16 ic][8 ocp][10 taps]     @ 14784  = 10240 B
//   z2 ull   [8 ocp][12 zr][2 px][33]    @ 25024  = 50688 B
#define XB_ST  33
#define WB_OFF 14784
#define Z2_OFF 25024
#define SMEM_BYTES 75712

__device__ __forceinline__ ull pack2(float v) {
    ull r; asm("mov.b64 %0, {%1, %1};" : "=l"(r) : "f"(v)); return r;
}
__device__ __forceinline__ ull packf2(float a, float b) {
    ull r; asm("mov.b64 %0, {%1, %2};" : "=l"(r) : "f"(a), "f"(b)); return r;
}
__device__ __forceinline__ void fma2(ull &acc, ull a, ull b) {
    asm("fma.rn.f32x2 %0, %1, %2, %0;" : "+l"(acc) : "l"(a), "l"(b));
}

__global__ __launch_bounds__(THREADS, 3)
void conv_resample_v7(const float* __restrict__ x, const float* __restrict__ f,
                      const float* __restrict__ w, float* __restrict__ out) {
    extern __shared__ char sm[];
    float* xb = (float*)sm;
    ull* wb = (ull*)(sm + WB_OFF);
    ull* zb = (ull*)(sm + Z2_OFF);

    const int tid = threadIdx.x;
    const int wid = tid >> 5, ln = tid & 31;
    const int ct = blockIdx.x % 9, rt = blockIdx.x / 9;
    const int g = blockIdx.y, n = blockIdx.z;
    const int a0 = rt * 4, b0 = ct * 30;

    // ---- stage 1: x tile [16 ic][7][33], zero halo/clamp ----
    const float* xg = x + ((size_t)(n * 128 + g * 16)) * 65536;
    for (int i = tid; i < 16 * 7 * 33; i += THREADS) {
        int c = i % 33;
        int rr = (i / 33) % 7;
        int ic = i / 231;
        int gm = a0 - 2 + rr, gq = b0 - 2 + c;
        float v = (gm >= 0 && gm < 256 && gq >= 0 && gq < 256)
                    ? xg[ic * 65536 + gm * 256 + gq] : 0.f;
        xb[(ic * 7 + rr) * XB_ST + c] = v;
    }
    // ---- weights: oc-pair f32x2, [ic][ocp][tap] ----
    const float* wgp = w + (size_t)g * 16 * 144;
    for (int i = tid; i < 16 * 8 * 9; i += THREADS) {
        int t = i % 9;
        int op = (i / 9) & 7;
        int ic = i / 72;
        wb[(ic * 8 + op) * 10 + t] =
            packf2(wgp[(op * 2 + 0) * 144 + ic * 9 + t],
                   wgp[(op * 2 + 1) * 144 + ic * 9 + t]);
    }
    float f0 = __ldg(f), f1 = __ldg(f + 1), f2 = __ldg(f + 2), f3 = __ldg(f + 3);
    ull gq0 = pack2(2.f * f3), gq1 = pack2(2.f * f2),
        gq2 = pack2(2.f * f1), gq3 = pack2(2.f * f0);
    __syncthreads();

    // ---- stage 2: warp = ocp; two sequential row-block units (3 position rows each) ----
    const int ocp = wid;
    const int pc = ln;
#pragma unroll 1
    for (int rb = 0; rb < 2; ++rb) {
        const int pr0 = rb * 3;
        ull acc[3][4];
#pragma unroll
        for (int r = 0; r < 3; ++r)
            acc[r][0] = acc[r][1] = acc[r][2] = acc[r][3] = 0ull;

#pragma unroll 1
        for (int ic = 0; ic < 16; ++ic) {
            const float* xr = xb + (ic * 7 + pr0) * XB_ST + pc;
            float va = xr[0], vb = xr[1];
            ull xa = pack2(va), xbv = pack2(vb);
            const ull* wp = wb + (ic * 8 + ocp) * 10;
            ull w0 = wp[0], w1 = wp[1], w2 = wp[2], w3 = wp[3], w4 = wp[4],
                w5 = wp[5], w6 = wp[6], w7 = wp[7], w8 = wp[8];
#pragma unroll
            for (int r = 0; r < 3; ++r) {
                xr += XB_ST;
                float vc = xr[0], vd = xr[1];
                ull ya = pack2(vc), yb = pack2(vd);
                fma2(acc[r][0], xa,  w0); fma2(acc[r][0], xbv, w2);
                fma2(acc[r][0], ya,  w6); fma2(acc[r][0], yb,  w8);
                fma2(acc[r][1], xbv, w1); fma2(acc[r][1], yb,  w7);
                fma2(acc[r][2], ya,  w3); fma2(acc[r][2], yb,  w5);
                fma2(acc[r][3], yb,  w4);
                xa = ya; xbv = yb;
            }
        }
        // z2 store: [ocp][zr][px][33]
        ull* z0 = zb + (((size_t)ocp * 12 + 2 * pr0) * 2) * XB_ST + pc;
#pragma unroll
        for (int r = 0; r < 3; ++r) {
            ull* zr0 = z0 + (size_t)(4 * r) * XB_ST;
            zr0[0]          = acc[r][0];   // zr even, px0
            zr0[XB_ST]      = acc[r][1];   // zr even, px1
            zr0[2 * XB_ST]  = acc[r][2];   // zr odd,  px0
            zr0[3 * XB_ST]  = acc[r][3];   // zr odd,  px1
        }
    }
    __syncthreads();

    // ---- stage 3: warp = ocp; lane m -> output cols 2m, 2m+1; vertical register rings ----
    {
        const int m = (ln < 30) ? ln : 29;
        const int gx = 2 * b0 + 2 * m;
        const bool valid = (ln < 30) && (gx < 512);

        // tap columns: A=(px1,m) D=(px0,m+1) B=(px1,m+1) E=(px0,m+2) C=(px1,m+2)
        const ull* zbase = zb + ((size_t)wid * 12 * 2) * XB_ST;
        const int oA = XB_ST + m, oD = m + 1, oB = XB_ST + m + 1,
                  oE = m + 2, oC = XB_ST + m + 2;

        ull rA[3], rD[3], rB[3], rE[3], rC[3];
#pragma unroll
        for (int j = 0; j < 3; ++j) {
            const ull* zr = zbase + (size_t)(2 * (j + 1)) * XB_ST;
            rA[j] = zr[oA]; rD[j] = zr[oD]; rB[j] = zr[oB];
            rE[j] = zr[oE]; rC[j] = zr[oC];
        }

        float* o0 = out + (((size_t)(n * 128 + g * 16 + wid * 2)) * 512
                           + (size_t)(2 * a0)) * 512 + gx;
#pragma unroll
        for (int oy = 0; oy < 8; ++oy) {
            const ull* zr = zbase + (size_t)(2 * (oy + 4)) * XB_ST;
            ull nA = zr[oA], nD = zr[oD], nB = zr[oB], nE = zr[oE], nC = zr[oC];
            ull TA = 0, TD = 0, TB = 0, TE = 0, TC = 0;
            fma2(TA, rA[0], gq0); fma2(TA, rA[1], gq1); fma2(TA, rA[2], gq2); fma2(TA, nA, gq3);
            fma2(TD, rD[0], gq0); fma2(TD, rD[1], gq1); fma2(TD, rD[2], gq2); fma2(TD, nD, gq3);
            fma2(TB, rB[0], gq0); fma2(TB, rB[1], gq1); fma2(TB, rB[2], gq2); fma2(TB, nB, gq3);
            fma2(TE, rE[0], gq0); fma2(TE, rE[1], gq1); fma2(TE, rE[2], gq2); fma2(TE, nE, gq3);
            fma2(TC, rC[0], gq0); fma2(TC, rC[1], gq1); fma2(TC, rC[2], gq2); fma2(TC, nC, gq3);
            rA[0] = rA[1]; rA[1] = rA[2]; rA[2] = nA;
            rD[0] = rD[1]; rD[1] = rD[2]; rD[2] = nD;
            rB[0] = rB[1]; rB[1] = rB[2]; rB[2] = nB;
            rE[0] = rE[1]; rE[1] = rE[2]; rE[2] = nE;
            rC[0] = rC[1]; rC[1] = rC[2]; rC[2] = nC;

            ull y0 = 0, y1 = 0;
            fma2(y0, TA, gq0); fma2(y0, TD, gq1); fma2(y0, TB, gq2); fma2(y0, TE, gq3);
            fma2(y1, TD, gq0); fma2(y1, TB, gq1); fma2(y1, TE, gq2); fma2(y1, TC, gq3);

            if (valid) {
                float2 p0 = *(float2*)&y0;      // (oc0, oc1) at col 2m
                float2 p1 = *(float2*)&y1;      // (oc0, oc1) at col 2m+1
                float* prow = o0 + (size_t)oy * 512;
                *(float2*)prow = make_float2(p0.x, p1.x);               // oc even plane
                *(float2*)(prow + 262144) = make_float2(p0.y, p1.y);    // oc odd plane
            }
        }
    }
}

extern "C" void kernel_launch(void* const* d_in, const int* in_sizes, int n_in,
                              void* d_out, int out_size) {
    const float* x = (const float*)d_in[0];
    const float* f = (const float*)d_in[1];
    const float* w = (const float*)d_in[2];
    float* out = (float*)d_out;

    cudaFuncSetAttribute(conv_resample_v7,
                         cudaFuncAttributeMaxDynamicSharedMemorySize, SMEM_BYTES);
    dim3 grid(64 * 9, 8, 4);   // 64 row-tiles x 9 col-tiles, groups, batch = 18432 CTAs
    conv_resample_v7<<<grid, THREADS, SMEM_BYTES>>>(x, f, w, out);
}